// round 13
// baseline (speedup 1.0000x reference)
#include <cuda_runtime.h>
#include <cuda_bf16.h>
#include <math.h>
#include <stdint.h>

// Problem dims (fixed)
#define BB 8
#define NN 100
#define DD 768
#define HH 768
#define TT 577
#define TH 24
#define SW (TH+1)         // 25
#define BN (BB*NN)        // 800
#define MPAD 896          // zero-padded A rows

// ---------------- scratch (device globals; zero-initialized) ---------------
__device__ float g_sat[BB * SW * SW * DD];
__device__ float g_ha[BN * HH];   // bias b1 folded in
__device__ float g_hb[BN * HH];
__device__ float g_part[4 * BB * NN * NN];   // pair k-split partials
__device__ uint4 g_pA_hi[MPAD * DD / 8];     // [896][768] bf16, rows >=800 zero
__device__ uint4 g_pA_lo[MPAD * DD / 8];
__device__ uint4 g_wt_hi[2 * HH * DD / 8];   // [1536][768] bf16 (row n, col k)
__device__ uint4 g_wt_lo[2 * HH * DD / 8];

// ---------------- helpers --------------------------------------------------
typedef unsigned long long ull;

__device__ __forceinline__ uint32_t smem_u32(const void* p) {
    uint32_t a;
    asm("{ .reg .u64 t; cvta.to.shared.u64 t, %1; cvt.u32.u64 %0, t; }"
        : "=r"(a) : "l"(p));
    return a;
}
__device__ __forceinline__ void ldm_x4(uint32_t* r, uint32_t addr) {
    asm volatile("ldmatrix.sync.aligned.m8n8.x4.shared.b16 {%0,%1,%2,%3}, [%4];"
                 : "=r"(r[0]), "=r"(r[1]), "=r"(r[2]), "=r"(r[3]) : "r"(addr));
}
__device__ __forceinline__ void ldm_x2(uint32_t* r, uint32_t addr) {
    asm volatile("ldmatrix.sync.aligned.m8n8.x2.shared.b16 {%0,%1}, [%2];"
                 : "=r"(r[0]), "=r"(r[1]) : "r"(addr));
}
__device__ __forceinline__ void mma16816(float* c, const uint32_t* a,
                                         const uint32_t* b) {
    asm volatile(
        "mma.sync.aligned.m16n8k16.row.col.f32.bf16.bf16.f32 "
        "{%0,%1,%2,%3}, {%4,%5,%6,%7}, {%8,%9}, {%0,%1,%2,%3};"
        : "+f"(c[0]), "+f"(c[1]), "+f"(c[2]), "+f"(c[3])
        : "r"(a[0]), "r"(a[1]), "r"(a[2]), "r"(a[3]), "r"(b[0]), "r"(b[1]));
}
__device__ __forceinline__ void cp16(uint32_t dst, const void* src) {
    asm volatile("cp.async.cg.shared.global [%0], [%1], 16;"
                 :: "r"(dst), "l"(src) : "memory");
}
#define CP_COMMIT() asm volatile("cp.async.commit_group;" ::: "memory")
#define CP_WAIT1()  asm volatile("cp.async.wait_group 1;" ::: "memory")

// packed f32x2 (Blackwell)
__device__ __forceinline__ ull pack2(float lo, float hi) {
    ull r;
    asm("mov.b64 %0, {%1, %2};" : "=l"(r) : "f"(lo), "f"(hi));
    return r;
}
__device__ __forceinline__ void unpack2(ull v, float& lo, float& hi) {
    asm("mov.b64 {%0, %1}, %2;" : "=f"(lo), "=f"(hi) : "l"(v));
}
__device__ __forceinline__ ull add2(ull a, ull b) {
    ull r;
    asm("add.rn.f32x2 %0, %1, %2;" : "=l"(r) : "l"(a), "l"(b));
    return r;
}
__device__ __forceinline__ void fma2(ull& d, ull a, ull b) {
    asm("fma.rn.f32x2 %0, %1, %2, %0;" : "+l"(d) : "l"(a), "l"(b));
}
__device__ __forceinline__ ull relu2(ull s) {
    float lo, hi;
    unpack2(s, lo, hi);
    lo = fmaxf(lo, 0.f);
    hi = fmaxf(hi, 0.f);
    return pack2(lo, hi);
}

// ---------------------------------------------------------------------------
// Kernel 1: fused SAT (row + col prefix) per (b, 32-d chunk).
// ---------------------------------------------------------------------------
#define DCH 32
__global__ void sat_fused_kernel(const float* __restrict__ pt) {
    extern __shared__ float sp[];     // [25][25][32]
    int b = blockIdx.x;
    int dc = blockIdx.y;
    int tid = threadIdx.x;
    int d = tid % DCH;
    int grp = tid / DCH;
    int dbase = dc * DCH;

    const float* base = pt + ((size_t)b * TT + 1) * DD + dbase + d;

    #pragma unroll
    for (int yy = 0; yy < 3; yy++) {
        int y = grp + yy * 8;
        const float* rp = base + (size_t)y * TH * DD;
        float* srow = sp + (size_t)(y + 1) * SW * DCH + d;
        float acc = 0.f;
        #pragma unroll
        for (int x = 0; x < TH; x++) {
            acc += rp[(size_t)x * DD];
            srow[(x + 1) * DCH] = acc;
        }
    }
    __syncthreads();

    float* gs = g_sat + ((size_t)b * SW * SW) * DD + dbase + d;
    #pragma unroll
    for (int xx = 0; xx < 3; xx++) {
        int x = grp + xx * 8;
        float acc = 0.f;
        #pragma unroll
        for (int y = 1; y < SW; y++) {
            acc += sp[((size_t)y * SW + (x + 1)) * DCH + d];
            gs[((size_t)y * SW + (x + 1)) * DD] = acc;
        }
    }
}

// ---------------------------------------------------------------------------
// Kernel 2: ROI mean via SAT lookup -> bf16 hi/lo split operand A.
// ---------------------------------------------------------------------------
__global__ void pool_lookup_kernel(const float* __restrict__ boxes,
                                   const int* __restrict__ imh,
                                   const int* __restrict__ imw) {
    int idx = blockIdx.x * 256 + threadIdx.x;
    int d = idx % DD;
    int bn = idx / DD;
    int b = bn / NN;

    const float* box = boxes + (size_t)bn * 4;
    float sizeW = (float)(*imw);
    float sizeH = (float)(*imh);

    int px1 = (int)floorf(floorf(box[0] * sizeW) / sizeW * (float)TH);
    int py1 = (int)floorf(floorf(box[1] * sizeH) / sizeH * (float)TH);
    int px2 = (int)floorf(floorf(box[2] * sizeW) / sizeW * (float)TH);
    int py2 = (int)floorf(floorf(box[3] * sizeH) / sizeH * (float)TH);
    px1 = min(max(px1, 0), TH - 1);
    py1 = min(max(py1, 0), TH - 1);
    px2 = min(max(px2, 1), TH);
    py2 = min(max(py2, 1), TH);
    if (px2 <= px1) px2 = px1 + 1;
    if (py2 <= py1) py2 = py1 + 1;

    float inv_cnt = 1.f / (float)((px2 - px1) * (py2 - py1));

    const float* S = g_sat + ((size_t)b * SW * SW) * DD + d;
    float s22 = S[((size_t)py2 * SW + px2) * DD];
    float s12 = S[((size_t)py1 * SW + px2) * DD];
    float s21 = S[((size_t)py2 * SW + px1) * DD];
    float s11 = S[((size_t)py1 * SW + px1) * DD];

    float p = (s22 - s12 - s21 + s11) * inv_cnt;
    __nv_bfloat16 hi = __float2bfloat16(p);
    __nv_bfloat16 lo = __float2bfloat16(p - __bfloat162float(hi));
    ((__nv_bfloat16*)g_pA_hi)[(size_t)bn * DD + d] = hi;
    ((__nv_bfloat16*)g_pA_lo)[(size_t)bn * DD + d] = lo;
}

// ---------------------------------------------------------------------------
// Kernel 3: transpose + bf16 hi/lo split of W1.
// ---------------------------------------------------------------------------
__global__ void convert_w_kernel(const float* __restrict__ W1) {
    __shared__ float tile[32][33];
    int s = blockIdx.z;
    int k0 = blockIdx.x * 32;
    int n0 = blockIdx.y * 32;
    int tx = threadIdx.x % 32, ty = threadIdx.x / 32;

    #pragma unroll
    for (int j = 0; j < 4; j++) {
        int k = k0 + ty + j * 8;
        tile[ty + j * 8][tx] = W1[((size_t)(s * DD + k)) * HH + n0 + tx];
    }
    __syncthreads();

    __nv_bfloat16* Whi = (__nv_bfloat16*)g_wt_hi;
    __nv_bfloat16* Wlo = (__nv_bfloat16*)g_wt_lo;
    #pragma unroll
    for (int j = 0; j < 4; j++) {
        int n = n0 + ty + j * 8;
        float v = tile[tx][ty + j * 8];
        __nv_bfloat16 hi = __float2bfloat16(v);
        __nv_bfloat16 lo = __float2bfloat16(v - __bfloat162float(hi));
        size_t o = ((size_t)(s * HH + n)) * DD + k0 + tx;
        Whi[o] = hi;
        Wlo[o] = lo;
    }
}

// ---------------------------------------------------------------------------
// Kernel 4: HMMA bf16 split GEMM with in-CTA k-split.
// CTA 64x64, 256 threads = 8 warps in 2 k-groups of 4.  Each group: warp
// tile 32x32, chunks [g*12, g*12+12), own cp.async double buffer.
// Group 1 accs reduced into group 0 via smem.  grid (24,13)=312, ~17 warps/SM.
// ---------------------------------------------------------------------------
#define KCH 32
#define NCHUNK (DD / KCH)     // 24
#define HCH (NCHUNK / 2)      // 12 chunks per group
#define PITCHB 80
#define T_AHI 0               // 64 rows * 80B = 5120
#define T_ALO 5120
#define T_BHI 10240
#define T_BLO 15360
#define BUFSZ 20480
#define GSMEM (4 * BUFSZ)     // 81920 dynamic

__global__ void __launch_bounds__(256)
hmma_gemm_kernel(const float* __restrict__ b1) {
    extern __shared__ __align__(16) char smem[];
    uint32_t sb = smem_u32(smem);

    int tid = threadIdx.x;                   // 0..255
    int wid = tid / 32, lid = tid % 32;
    int g = wid >> 2;                        // k-group 0/1
    int wg = wid & 3;                        // warp within group
    int wy = wg & 1, wx = wg >> 1;           // warp tile (wy*32 m, wx*32 n)
    int tl = tid & 127;                      // thread within group

    int nt = blockIdx.x;                     // 0..23
    int m0 = blockIdx.y * 64;
    int nrow0 = nt * 64;                     // row base into Wt

    const char* Ahi = (const char*)g_pA_hi;
    const char* Alo = (const char*)g_pA_lo;
    const char* Bhi = (const char*)g_wt_hi;
    const char* Blo = (const char*)g_wt_lo;

    // group g buffers live at [g*2*BUFSZ, g*2*BUFSZ + 2*BUFSZ)
    uint32_t gbase = sb + (uint32_t)g * 2 * BUFSZ;

    // cp.async: 64 rows x 4 granules = 256 slots, 2 iters of 128 group-threads
    auto load_chunk = [&](int buf, int ch) {     // ch is group-local 0..11
        uint32_t bufb = gbase + buf * BUFSZ;
        int kb = (g * HCH + ch) * KCH;
        #pragma unroll
        for (int t = 0; t < 2; t++) {
            int idx = tl + t * 128;
            int r = idx >> 2, gr = idx & 3;
            uint32_t off = (uint32_t)(r * PITCHB + gr * 16);
            size_t oa = ((size_t)(m0 + r) * DD + kb) * 2 + (size_t)gr * 16;
            size_t ob = ((size_t)(nrow0 + r) * DD + kb) * 2 + (size_t)gr * 16;
            cp16(bufb + T_AHI + off, Ahi + oa);
            cp16(bufb + T_ALO + off, Alo + oa);
            cp16(bufb + T_BHI + off, Bhi + ob);
            cp16(bufb + T_BLO + off, Blo + ob);
        }
    };

    float acc[2][4][4] = {};                 // warp 32x32: mf2 x nf4

    load_chunk(0, 0);
    CP_COMMIT();
    load_chunk(1, 1);
    CP_COMMIT();

    int la_row = lid % 16, la_blk = lid / 16;
    int lb_row = lid % 8, lb_blk = (lid / 8) & 1;

    for (int ch = 0; ch < HCH; ch++) {
        CP_WAIT1();
        __syncthreads();

        uint32_t bufb = gbase + (ch & 1) * BUFSZ;

        #pragma unroll
        for (int ks = 0; ks < 2; ks++) {
            int kofs = ks * 16;
            uint32_t ahi[2][4], alo[2][4], bhi[4][2], blo[4][2];

            #pragma unroll
            for (int mf = 0; mf < 2; mf++) {
                uint32_t ad = bufb + (uint32_t)((wy * 32 + mf * 16 + la_row) * PITCHB
                                                + (kofs + la_blk * 8) * 2);
                ldm_x4(ahi[mf], T_AHI + ad);
                ldm_x4(alo[mf], T_ALO + ad);
            }
            #pragma unroll
            for (int nf = 0; nf < 4; nf++) {
                uint32_t bd = bufb + (uint32_t)((wx * 32 + nf * 8 + lb_row) * PITCHB
                                                + (kofs + lb_blk * 8) * 2);
                ldm_x2(bhi[nf], T_BHI + bd);
                ldm_x2(blo[nf], T_BLO + bd);
            }

            #pragma unroll
            for (int mf = 0; mf < 2; mf++) {
                #pragma unroll
                for (int nf = 0; nf < 4; nf++) {
                    mma16816(acc[mf][nf], ahi[mf], bhi[nf]);
                    mma16816(acc[mf][nf], alo[mf], bhi[nf]);
                    mma16816(acc[mf][nf], ahi[mf], blo[nf]);
                }
            }
        }
        __syncthreads();

        if (ch + 2 < HCH) load_chunk(ch & 1, ch + 2);
        CP_COMMIT();
    }

    // Cross-group reduction: group 1 spills accs, group 0 adds.
    // Layout red[q][tl] (q = 0..31): conflict-free.
    float* red = (float*)smem;
    __syncthreads();                         // all loads/MMAs done both groups
    if (g == 1) {
        int q = 0;
        #pragma unroll
        for (int mf = 0; mf < 2; mf++)
            #pragma unroll
            for (int nf = 0; nf < 4; nf++)
                #pragma unroll
                for (int e = 0; e < 4; e++)
                    red[(q++) * 128 + tl] = acc[mf][nf][e];
    }
    __syncthreads();
    if (g == 1) return;

    {
        int q = 0;
        #pragma unroll
        for (int mf = 0; mf < 2; mf++)
            #pragma unroll
            for (int nf = 0; nf < 4; nf++)
                #pragma unroll
                for (int e = 0; e < 4; e++)
                    acc[mf][nf][e] += red[(q++) * 128 + tl];
    }

    // Epilogue: fold b1 for the ha half, store float2 pairs
    bool is_ha = (nt < 12);
    float* C = is_ha ? g_ha : g_hb;
    int n0 = (is_ha ? nt : nt - 12) * 64;

    #pragma unroll
    for (int mf = 0; mf < 2; mf++) {
        #pragma unroll
        for (int nf = 0; nf < 4; nf++) {
            int m = m0 + wy * 32 + mf * 16 + lid / 4;
            int n = n0 + wx * 32 + nf * 8 + 2 * (lid % 4);
            float2 bia = make_float2(0.f, 0.f);
            if (is_ha) bia = *(const float2*)(b1 + n);
            if (m < BN) {
                float2 v = make_float2(acc[mf][nf][0] + bia.x,
                                       acc[mf][nf][1] + bia.y);
                *(float2*)(C + (size_t)m * HH + n) = v;
            }
            if (m + 8 < BN) {
                float2 v = make_float2(acc[mf][nf][2] + bia.x,
                                       acc[mf][nf][3] + bia.y);
                *(float2*)(C + (size_t)(m + 8) * HH + n) = v;
            }
        }
    }
}

// ---------------------------------------------------------------------------
// Kernel 5a: pairwise relu-dot partials, k-split into 4 quarters.
// ---------------------------------------------------------------------------
#define KC 64
#define KQ (HH / 4)           // 192
__global__ void pair_part_kernel(const float* __restrict__ W2) {
    int z = blockIdx.z;
    int b = z >> 2;
    int kq = z & 3;
    int i0 = blockIdx.y * 32;
    int j0 = blockIdx.x * 32;

    __shared__ float has[32][KC + 4];
    __shared__ float hbs[32][KC + 4];
    __shared__ float w2s[KC];

    int tid = threadIdx.x;
    int tx = tid % 16, ty = tid / 16;

    ull acc[2][2];
    acc[0][0] = acc[0][1] = acc[1][0] = acc[1][1] = pack2(0.f, 0.f);

    int kbeg = kq * KQ;
    for (int k0 = kbeg; k0 < kbeg + KQ; k0 += KC) {
        #pragma unroll
        for (int t = 0; t < 2; t++) {
            int idx = tid + t * 256;
            int r = idx / 16, c4 = idx % 16;
            int i = i0 + r;
            float4 va = make_float4(0.f, 0.f, 0.f, 0.f);
            if (i < NN) va = *(const float4*)&g_ha[((size_t)b * NN + i) * HH + k0 + c4 * 4];
            *(float4*)&has[r][c4 * 4] = va;
            int j = j0 + r;
            float4 vb = make_float4(0.f, 0.f, 0.f, 0.f);
            if (j < NN) vb = *(const float4*)&g_hb[((size_t)b * NN + j) * HH + k0 + c4 * 4];
            *(float4*)&hbs[r][c4 * 4] = vb;
        }
        if (tid < KC / 4)
            *(float4*)&w2s[tid * 4] = *(const float4*)&W2[k0 + tid * 4];
        __syncthreads();

        #pragma unroll
        for (int kk = 0; kk < KC; kk += 4) {
            float4 a0 = *(const float4*)&has[ty * 2][kk];
            float4 a1 = *(const float4*)&has[ty * 2 + 1][kk];
            float4 c0 = *(const float4*)&hbs[tx * 2][kk];
            float4 c1 = *(const float4*)&hbs[tx * 2 + 1][kk];
            float4 w  = *(const float4*)&w2s[kk];

            ull a0p0 = pack2(a0.x, a0.y), a0p1 = pack2(a0.z, a0.w);
            ull a1p0 = pack2(a1.x, a1.y), a1p1 = pack2(a1.z, a1.w);
            ull c0p0 = pack2(c0.x, c0.y), c0p1 = pack2(c0.z, c0.w);
            ull c1p0 = pack2(c1.x, c1.y), c1p1 = pack2(c1.z, c1.w);
            ull wp0  = pack2(w.x, w.y),   wp1  = pack2(w.z, w.w);

            fma2(acc[0][0], relu2(add2(a0p0, c0p0)), wp0);
            fma2(acc[0][0], relu2(add2(a0p1, c0p1)), wp1);
            fma2(acc[0][1], relu2(add2(a0p0, c1p0)), wp0);
            fma2(acc[0][1], relu2(add2(a0p1, c1p1)), wp1);
            fma2(acc[1][0], relu2(add2(a1p0, c0p0)), wp0);
            fma2(acc[1][0], relu2(add2(a1p1, c0p1)), wp1);
            fma2(acc[1][1], relu2(add2(a1p0, c1p0)), wp0);
            fma2(acc[1][1], relu2(add2(a1p1, c1p1)), wp1);
        }
        __syncthreads();
    }

    float* P = g_part + (size_t)kq * BB * NN * NN + (size_t)b * NN * NN;
    #pragma unroll
    for (int ii = 0; ii < 2; ii++) {
        #pragma unroll
        for (int jj = 0; jj < 2; jj++) {
            int i = i0 + ty * 2 + ii;
            int j = j0 + tx * 2 + jj;
            if (i < NN && j < NN) {
                float lo, hi;
                unpack2(acc[ii][jj], lo, hi);
                P[(size_t)i * NN + j] = lo + hi;
            }
        }
    }
}

// ---------------------------------------------------------------------------
// Kernel 5b: sum 4 partials + sigmoid.
// ---------------------------------------------------------------------------
__global__ void pair_final_kernel(const float* __restrict__ b2,
                                  float* __restrict__ out) {
    int idx = blockIdx.x * 256 + threadIdx.x;
    if (idx >= BB * NN * NN) return;
    const size_t S = (size_t)BB * NN * NN;
    float x = g_part[idx] + g_part[S + idx] + g_part[2 * S + idx]
            + g_part[3 * S + idx] + b2[0];
    out[idx] = 1.f / (1.f + expf(-x));
}

// ---------------------------------------------------------------------------
// Launch.  inputs: patch_tokens, boxes, W1, b1, W2, b2, img_h, img_w
// ---------------------------------------------------------------------------
extern "C" void kernel_launch(void* const* d_in, const int* in_sizes, int n_in,
                              void* d_out, int out_size) {
    const float* pt    = (const float*)d_in[0];
    const float* boxes = (const float*)d_in[1];
    const float* W1    = (const float*)d_in[2];
    const float* b1    = (const float*)d_in[3];
    const float* W2    = (const float*)d_in[4];
    const float* b2    = (const float*)d_in[5];
    const int*   imh   = (const int*)d_in[6];
    const int*   imw   = (const int*)d_in[7];
    float* out = (float*)d_out;

    cudaFuncSetAttribute(sat_fused_kernel,
                         cudaFuncAttributeMaxDynamicSharedMemorySize,
                         SW * SW * DCH * (int)sizeof(float));
    cudaFuncSetAttribute(hmma_gemm_kernel,
                         cudaFuncAttributeMaxDynamicSharedMemorySize, GSMEM);

    dim3 gs(BB, DD / DCH);            // (8, 24)
    sat_fused_kernel<<<gs, 256, SW * SW * DCH * sizeof(float)>>>(pt);

    pool_lookup_kernel<<<(BN * DD) / 256, 256>>>(boxes, imh, imw);

    dim3 gw(DD / 32, HH / 32, 2);     // (24, 24, 2)
    convert_w_kernel<<<gw, 256>>>(W1);

    dim3 gg(2 * HH / 64, (BN + 63) / 64);   // (24, 13) = 312 CTAs
    hmma_gemm_kernel<<<gg, 256, GSMEM>>>(b1);

    dim3 gp((NN + 31) / 32, (NN + 31) / 32, BB * 4);  // (4, 4, 32)
    pair_part_kernel<<<gp, 256>>>(W2);

    pair_final_kernel<<<(BB * NN * NN + 255) / 256, 256>>>(b2, out);
}

// round 14
// speedup vs baseline: 1.3236x; 1.3236x over previous
#include <cuda_runtime.h>
#include <cuda_fp16.h>
#include <math.h>
#include <stdint.h>

// Problem dims (fixed)
#define BB 8
#define NN 100
#define DD 768
#define HH 768
#define TT 577
#define TH 24
#define SW (TH+1)         // 25
#define BN (BB*NN)        // 800
#define MPAD 896          // zero-padded A rows

// ---------------- scratch (device globals; zero-initialized) ---------------
__device__ float g_sat[BB * SW * SW * DD];
__device__ float g_ha[BN * HH];   // bias b1 folded in
__device__ float g_hb[BN * HH];
__device__ float g_part[4 * BB * NN * NN];   // pair k-split partials
__device__ uint4 g_pA[MPAD * DD / 8];        // [896][768] fp16, rows >=800 zero
__device__ uint4 g_wt[2 * HH * DD / 8];      // [1536][768] fp16 (row n, col k)

// ---------------- helpers --------------------------------------------------
typedef unsigned long long ull;

__device__ __forceinline__ uint32_t smem_u32(const void* p) {
    uint32_t a;
    asm("{ .reg .u64 t; cvta.to.shared.u64 t, %1; cvt.u32.u64 %0, t; }"
        : "=r"(a) : "l"(p));
    return a;
}
__device__ __forceinline__ void ldm_x4(uint32_t* r, uint32_t addr) {
    asm volatile("ldmatrix.sync.aligned.m8n8.x4.shared.b16 {%0,%1,%2,%3}, [%4];"
                 : "=r"(r[0]), "=r"(r[1]), "=r"(r[2]), "=r"(r[3]) : "r"(addr));
}
__device__ __forceinline__ void ldm_x2(uint32_t* r, uint32_t addr) {
    asm volatile("ldmatrix.sync.aligned.m8n8.x2.shared.b16 {%0,%1}, [%2];"
                 : "=r"(r[0]), "=r"(r[1]) : "r"(addr));
}
__device__ __forceinline__ void mma16816h(float* c, const uint32_t* a,
                                          const uint32_t* b) {
    asm volatile(
        "mma.sync.aligned.m16n8k16.row.col.f32.f16.f16.f32 "
        "{%0,%1,%2,%3}, {%4,%5,%6,%7}, {%8,%9}, {%0,%1,%2,%3};"
        : "+f"(c[0]), "+f"(c[1]), "+f"(c[2]), "+f"(c[3])
        : "r"(a[0]), "r"(a[1]), "r"(a[2]), "r"(a[3]), "r"(b[0]), "r"(b[1]));
}
__device__ __forceinline__ void cp16(uint32_t dst, const void* src) {
    asm volatile("cp.async.cg.shared.global [%0], [%1], 16;"
                 :: "r"(dst), "l"(src) : "memory");
}
#define CP_COMMIT() asm volatile("cp.async.commit_group;" ::: "memory")
#define CP_WAIT1()  asm volatile("cp.async.wait_group 1;" ::: "memory")

// packed f32x2 (Blackwell)
__device__ __forceinline__ ull pack2(float lo, float hi) {
    ull r;
    asm("mov.b64 %0, {%1, %2};" : "=l"(r) : "f"(lo), "f"(hi));
    return r;
}
__device__ __forceinline__ void unpack2(ull v, float& lo, float& hi) {
    asm("mov.b64 {%0, %1}, %2;" : "=f"(lo), "=f"(hi) : "l"(v));
}
__device__ __forceinline__ ull add2(ull a, ull b) {
    ull r;
    asm("add.rn.f32x2 %0, %1, %2;" : "=l"(r) : "l"(a), "l"(b));
    return r;
}
__device__ __forceinline__ void fma2(ull& d, ull a, ull b) {
    asm("fma.rn.f32x2 %0, %1, %2, %0;" : "+l"(d) : "l"(a), "l"(b));
}
__device__ __forceinline__ ull relu2(ull s) {
    float lo, hi;
    unpack2(s, lo, hi);
    lo = fmaxf(lo, 0.f);
    hi = fmaxf(hi, 0.f);
    return pack2(lo, hi);
}

// ---------------------------------------------------------------------------
// Kernel 1: fused SAT (row + col prefix) per (b, 32-d chunk).
// ---------------------------------------------------------------------------
#define DCH 32
__global__ void sat_fused_kernel(const float* __restrict__ pt) {
    extern __shared__ float sp[];     // [25][25][32]
    int b = blockIdx.x;
    int dc = blockIdx.y;
    int tid = threadIdx.x;
    int d = tid % DCH;
    int grp = tid / DCH;
    int dbase = dc * DCH;

    const float* base = pt + ((size_t)b * TT + 1) * DD + dbase + d;

    #pragma unroll
    for (int yy = 0; yy < 3; yy++) {
        int y = grp + yy * 8;
        const float* rp = base + (size_t)y * TH * DD;
        float* srow = sp + (size_t)(y + 1) * SW * DCH + d;
        float acc = 0.f;
        #pragma unroll
        for (int x = 0; x < TH; x++) {
            acc += rp[(size_t)x * DD];
            srow[(x + 1) * DCH] = acc;
        }
    }
    __syncthreads();

    float* gs = g_sat + ((size_t)b * SW * SW) * DD + dbase + d;
    #pragma unroll
    for (int xx = 0; xx < 3; xx++) {
        int x = grp + xx * 8;
        float acc = 0.f;
        #pragma unroll
        for (int y = 1; y < SW; y++) {
            acc += sp[((size_t)y * SW + (x + 1)) * DCH + d];
            gs[((size_t)y * SW + (x + 1)) * DD] = acc;
        }
    }
}

// ---------------------------------------------------------------------------
// Kernel 2: ROI mean via SAT lookup -> fp16 operand A.
// ---------------------------------------------------------------------------
__global__ void pool_lookup_kernel(const float* __restrict__ boxes,
                                   const int* __restrict__ imh,
                                   const int* __restrict__ imw) {
    int idx = blockIdx.x * 256 + threadIdx.x;
    int d = idx % DD;
    int bn = idx / DD;
    int b = bn / NN;

    const float* box = boxes + (size_t)bn * 4;
    float sizeW = (float)(*imw);
    float sizeH = (float)(*imh);

    int px1 = (int)floorf(floorf(box[0] * sizeW) / sizeW * (float)TH);
    int py1 = (int)floorf(floorf(box[1] * sizeH) / sizeH * (float)TH);
    int px2 = (int)floorf(floorf(box[2] * sizeW) / sizeW * (float)TH);
    int py2 = (int)floorf(floorf(box[3] * sizeH) / sizeH * (float)TH);
    px1 = min(max(px1, 0), TH - 1);
    py1 = min(max(py1, 0), TH - 1);
    px2 = min(max(px2, 1), TH);
    py2 = min(max(py2, 1), TH);
    if (px2 <= px1) px2 = px1 + 1;
    if (py2 <= py1) py2 = py1 + 1;

    float inv_cnt = 1.f / (float)((px2 - px1) * (py2 - py1));

    const float* S = g_sat + ((size_t)b * SW * SW) * DD + d;
    float s22 = S[((size_t)py2 * SW + px2) * DD];
    float s12 = S[((size_t)py1 * SW + px2) * DD];
    float s21 = S[((size_t)py2 * SW + px1) * DD];
    float s11 = S[((size_t)py1 * SW + px1) * DD];

    float p = (s22 - s12 - s21 + s11) * inv_cnt;
    ((__half*)g_pA)[(size_t)bn * DD + d] = __float2half_rn(p);
}

// ---------------------------------------------------------------------------
// Kernel 3: transpose W1 -> fp16.
// ---------------------------------------------------------------------------
__global__ void convert_w_kernel(const float* __restrict__ W1) {
    __shared__ float tile[32][33];
    int s = blockIdx.z;
    int k0 = blockIdx.x * 32;
    int n0 = blockIdx.y * 32;
    int tx = threadIdx.x % 32, ty = threadIdx.x / 32;

    #pragma unroll
    for (int j = 0; j < 4; j++) {
        int k = k0 + ty + j * 8;
        tile[ty + j * 8][tx] = W1[((size_t)(s * DD + k)) * HH + n0 + tx];
    }
    __syncthreads();

    __half* W = (__half*)g_wt;
    #pragma unroll
    for (int j = 0; j < 4; j++) {
        int n = n0 + ty + j * 8;
        float v = tile[tx][ty + j * 8];
        W[((size_t)(s * HH + n)) * DD + k0 + tx] = __float2half_rn(v);
    }
}

// ---------------------------------------------------------------------------
// Kernel 4: HMMA fp16 GEMM (single MMA per product).
// CTA 64x64, 128 threads = 4 warps, each 32x32.  cp.async double buffer.
// grid (24, 13) = 312 CTAs.
// ---------------------------------------------------------------------------
#define KCH 32
#define NCHUNK (DD / KCH)     // 24
#define PITCHB 80             // 32 fp16 = 64B + 16B pad
#define T_A 0                 // 64 rows * 80B = 5120
#define T_B 5120
#define BUFSZ 10240
#define GSMEM (2 * BUFSZ)     // 20480

__global__ void __launch_bounds__(128)
hmma_gemm_kernel(const float* __restrict__ b1) {
    __shared__ __align__(16) char smem[GSMEM];
    uint32_t sb = smem_u32(smem);

    int tid = threadIdx.x;                   // 0..127
    int wid = tid / 32, lid = tid % 32;
    int wy = wid & 1, wx = wid >> 1;         // warp tile (wy*32 m, wx*32 n)

    int nt = blockIdx.x;                     // 0..23
    int m0 = blockIdx.y * 64;
    int nrow0 = nt * 64;                     // row base into Wt

    const char* A = (const char*)g_pA;
    const char* B = (const char*)g_wt;

    // cp.async mapping: 64 rows x 4 granules (16B) = 256 slots, 2 iters
    auto load_chunk = [&](int buf, int ch) {
        uint32_t bufb = sb + buf * BUFSZ;
        int kb = ch * KCH;
        #pragma unroll
        for (int t = 0; t < 2; t++) {
            int idx = tid + t * 128;
            int r = idx >> 2, g = idx & 3;
            uint32_t off = (uint32_t)(r * PITCHB + g * 16);
            size_t oa = ((size_t)(m0 + r) * DD + kb) * 2 + (size_t)g * 16;
            size_t ob = ((size_t)(nrow0 + r) * DD + kb) * 2 + (size_t)g * 16;
            cp16(bufb + T_A + off, A + oa);
            cp16(bufb + T_B + off, B + ob);
        }
    };

    float acc[2][4][4] = {};                 // warp 32x32: mf2 x nf4

    load_chunk(0, 0);
    CP_COMMIT();
    load_chunk(1, 1);
    CP_COMMIT();

    int la_row = lid % 16, la_blk = lid / 16;
    int lb_row = lid % 8, lb_blk = (lid / 8) & 1;

    for (int ch = 0; ch < NCHUNK; ch++) {
        CP_WAIT1();
        __syncthreads();

        uint32_t bufb = sb + (ch & 1) * BUFSZ;

        #pragma unroll
        for (int ks = 0; ks < 2; ks++) {
            int kofs = ks * 16;
            uint32_t a[2][4], b[4][2];

            #pragma unroll
            for (int mf = 0; mf < 2; mf++) {
                uint32_t ad = bufb + (uint32_t)((wy * 32 + mf * 16 + la_row) * PITCHB
                                                + (kofs + la_blk * 8) * 2);
                ldm_x4(a[mf], T_A + ad);
            }
            #pragma unroll
            for (int nf = 0; nf < 4; nf++) {
                uint32_t bd = bufb + (uint32_t)((wx * 32 + nf * 8 + lb_row) * PITCHB
                                                + (kofs + lb_blk * 8) * 2);
                ldm_x2(b[nf], T_B + bd);
            }

            #pragma unroll
            for (int mf = 0; mf < 2; mf++) {
                #pragma unroll
                for (int nf = 0; nf < 4; nf++) {
                    mma16816h(acc[mf][nf], a[mf], b[nf]);
                }
            }
        }
        __syncthreads();

        if (ch + 2 < NCHUNK) load_chunk(ch & 1, ch + 2);
        CP_COMMIT();
    }

    // Epilogue: fold b1 for the ha half, store float2 pairs
    bool is_ha = (nt < 12);
    float* C = is_ha ? g_ha : g_hb;
    int n0 = (is_ha ? nt : nt - 12) * 64;

    #pragma unroll
    for (int mf = 0; mf < 2; mf++) {
        #pragma unroll
        for (int nf = 0; nf < 4; nf++) {
            int m = m0 + wy * 32 + mf * 16 + lid / 4;
            int n = n0 + wx * 32 + nf * 8 + 2 * (lid % 4);
            float2 bia = make_float2(0.f, 0.f);
            if (is_ha) bia = *(const float2*)(b1 + n);
            if (m < BN) {
                float2 v = make_float2(acc[mf][nf][0] + bia.x,
                                       acc[mf][nf][1] + bia.y);
                *(float2*)(C + (size_t)m * HH + n) = v;
            }
            if (m + 8 < BN) {
                float2 v = make_float2(acc[mf][nf][2] + bia.x,
                                       acc[mf][nf][3] + bia.y);
                *(float2*)(C + (size_t)(m + 8) * HH + n) = v;
            }
        }
    }
}

// ---------------------------------------------------------------------------
// Kernel 5a: pairwise relu-dot partials, k-split into 4 quarters.
// ---------------------------------------------------------------------------
#define KC 64
#define KQ (HH / 4)           // 192
__global__ void pair_part_kernel(const float* __restrict__ W2) {
    int z = blockIdx.z;
    int b = z >> 2;
    int kq = z & 3;
    int i0 = blockIdx.y * 32;
    int j0 = blockIdx.x * 32;

    __shared__ float has[32][KC + 4];
    __shared__ float hbs[32][KC + 4];
    __shared__ float w2s[KC];

    int tid = threadIdx.x;
    int tx = tid % 16, ty = tid / 16;

    ull acc[2][2];
    acc[0][0] = acc[0][1] = acc[1][0] = acc[1][1] = pack2(0.f, 0.f);

    int kbeg = kq * KQ;
    for (int k0 = kbeg; k0 < kbeg + KQ; k0 += KC) {
        #pragma unroll
        for (int t = 0; t < 2; t++) {
            int idx = tid + t * 256;
            int r = idx / 16, c4 = idx % 16;
            int i = i0 + r;
            float4 va = make_float4(0.f, 0.f, 0.f, 0.f);
            if (i < NN) va = *(const float4*)&g_ha[((size_t)b * NN + i) * HH + k0 + c4 * 4];
            *(float4*)&has[r][c4 * 4] = va;
            int j = j0 + r;
            float4 vb = make_float4(0.f, 0.f, 0.f, 0.f);
            if (j < NN) vb = *(const float4*)&g_hb[((size_t)b * NN + j) * HH + k0 + c4 * 4];
            *(float4*)&hbs[r][c4 * 4] = vb;
        }
        if (tid < KC / 4)
            *(float4*)&w2s[tid * 4] = *(const float4*)&W2[k0 + tid * 4];
        __syncthreads();

        #pragma unroll
        for (int kk = 0; kk < KC; kk += 4) {
            float4 a0 = *(const float4*)&has[ty * 2][kk];
            float4 a1 = *(const float4*)&has[ty * 2 + 1][kk];
            float4 c0 = *(const float4*)&hbs[tx * 2][kk];
            float4 c1 = *(const float4*)&hbs[tx * 2 + 1][kk];
            float4 w  = *(const float4*)&w2s[kk];

            ull a0p0 = pack2(a0.x, a0.y), a0p1 = pack2(a0.z, a0.w);
            ull a1p0 = pack2(a1.x, a1.y), a1p1 = pack2(a1.z, a1.w);
            ull c0p0 = pack2(c0.x, c0.y), c0p1 = pack2(c0.z, c0.w);
            ull c1p0 = pack2(c1.x, c1.y), c1p1 = pack2(c1.z, c1.w);
            ull wp0  = pack2(w.x, w.y),   wp1  = pack2(w.z, w.w);

            fma2(acc[0][0], relu2(add2(a0p0, c0p0)), wp0);
            fma2(acc[0][0], relu2(add2(a0p1, c0p1)), wp1);
            fma2(acc[0][1], relu2(add2(a0p0, c1p0)), wp0);
            fma2(acc[0][1], relu2(add2(a0p1, c1p1)), wp1);
            fma2(acc[1][0], relu2(add2(a1p0, c0p0)), wp0);
            fma2(acc[1][0], relu2(add2(a1p1, c0p1)), wp1);
            fma2(acc[1][1], relu2(add2(a1p0, c1p0)), wp0);
            fma2(acc[1][1], relu2(add2(a1p1, c1p1)), wp1);
        }
        __syncthreads();
    }

    float* P = g_part + (size_t)kq * BB * NN * NN + (size_t)b * NN * NN;
    #pragma unroll
    for (int ii = 0; ii < 2; ii++) {
        #pragma unroll
        for (int jj = 0; jj < 2; jj++) {
            int i = i0 + ty * 2 + ii;
            int j = j0 + tx * 2 + jj;
            if (i < NN && j < NN) {
                float lo, hi;
                unpack2(acc[ii][jj], lo, hi);
                P[(size_t)i * NN + j] = lo + hi;
            }
        }
    }
}

// ---------------------------------------------------------------------------
// Kernel 5b: sum 4 partials + sigmoid.
// ---------------------------------------------------------------------------
__global__ void pair_final_kernel(const float* __restrict__ b2,
                                  float* __restrict__ out) {
    int idx = blockIdx.x * 256 + threadIdx.x;
    if (idx >= BB * NN * NN) return;
    const size_t S = (size_t)BB * NN * NN;
    float x = g_part[idx] + g_part[S + idx] + g_part[2 * S + idx]
            + g_part[3 * S + idx] + b2[0];
    out[idx] = 1.f / (1.f + expf(-x));
}

// ---------------------------------------------------------------------------
// Launch.  inputs: patch_tokens, boxes, W1, b1, W2, b2, img_h, img_w
// ---------------------------------------------------------------------------
extern "C" void kernel_launch(void* const* d_in, const int* in_sizes, int n_in,
                              void* d_out, int out_size) {
    const float* pt    = (const float*)d_in[0];
    const float* boxes = (const float*)d_in[1];
    const float* W1    = (const float*)d_in[2];
    const float* b1    = (const float*)d_in[3];
    const float* W2    = (const float*)d_in[4];
    const float* b2    = (const float*)d_in[5];
    const int*   imh   = (const int*)d_in[6];
    const int*   imw   = (const int*)d_in[7];
    float* out = (float*)d_out;

    cudaFuncSetAttribute(sat_fused_kernel,
                         cudaFuncAttributeMaxDynamicSharedMemorySize,
                         SW * SW * DCH * (int)sizeof(float));

    dim3 gs(BB, DD / DCH);            // (8, 24)
    sat_fused_kernel<<<gs, 256, SW * SW * DCH * sizeof(float)>>>(pt);

    pool_lookup_kernel<<<(BN * DD) / 256, 256>>>(boxes, imh, imw);

    dim3 gw(DD / 32, HH / 32, 2);     // (24, 24, 2)
    convert_w_kernel<<<gw, 256>>>(W1);

    dim3 gg(2 * HH / 64, (BN + 63) / 64);   // (24, 13) = 312 CTAs
    hmma_gemm_kernel<<<gg, 128>>>(b1);

    dim3 gp((NN + 31) / 32, (NN + 31) / 32, BB * 4);  // (4, 4, 32)
    pair_part_kernel<<<gp, 256>>>(W2);

    pair_final_kernel<<<(BB * NN * NN + 255) / 256, 256>>>(b2, out);
}

// round 15
// speedup vs baseline: 1.3746x; 1.0385x over previous
#include <cuda_runtime.h>
#include <cuda_fp16.h>
#include <math.h>
#include <stdint.h>

// Problem dims (fixed)
#define BB 8
#define NN 100
#define DD 768
#define HH 768
#define TT 577
#define TH 24
#define SW (TH+1)         // 25
#define BN (BB*NN)        // 800
#define MPAD 896          // zero-padded A rows

// ---------------- scratch (device globals; zero-initialized) ---------------
__device__ float g_sat[BB * SW * SW * DD];
__device__ float g_ha[BN * HH];   // bias b1 folded in
__device__ float g_hb[BN * HH];
__device__ float g_part[4 * BB * NN * NN];   // pair k-split partials
__device__ uint4 g_pA[MPAD * DD / 8];        // [896][768] fp16, rows >=800 zero
__device__ uint4 g_wt[2 * HH * DD / 8];      // [1536][768] fp16 (row n, col k)

// ---------------- helpers --------------------------------------------------
typedef unsigned long long ull;

__device__ __forceinline__ uint32_t smem_u32(const void* p) {
    uint32_t a;
    asm("{ .reg .u64 t; cvta.to.shared.u64 t, %1; cvt.u32.u64 %0, t; }"
        : "=r"(a) : "l"(p));
    return a;
}
__device__ __forceinline__ void ldm_x4(uint32_t* r, uint32_t addr) {
    asm volatile("ldmatrix.sync.aligned.m8n8.x4.shared.b16 {%0,%1,%2,%3}, [%4];"
                 : "=r"(r[0]), "=r"(r[1]), "=r"(r[2]), "=r"(r[3]) : "r"(addr));
}
__device__ __forceinline__ void ldm_x2(uint32_t* r, uint32_t addr) {
    asm volatile("ldmatrix.sync.aligned.m8n8.x2.shared.b16 {%0,%1}, [%2];"
                 : "=r"(r[0]), "=r"(r[1]) : "r"(addr));
}
__device__ __forceinline__ void mma16816h(float* c, const uint32_t* a,
                                          const uint32_t* b) {
    asm volatile(
        "mma.sync.aligned.m16n8k16.row.col.f32.f16.f16.f32 "
        "{%0,%1,%2,%3}, {%4,%5,%6,%7}, {%8,%9}, {%0,%1,%2,%3};"
        : "+f"(c[0]), "+f"(c[1]), "+f"(c[2]), "+f"(c[3])
        : "r"(a[0]), "r"(a[1]), "r"(a[2]), "r"(a[3]), "r"(b[0]), "r"(b[1]));
}
__device__ __forceinline__ void cp16(uint32_t dst, const void* src) {
    asm volatile("cp.async.cg.shared.global [%0], [%1], 16;"
                 :: "r"(dst), "l"(src) : "memory");
}
#define CP_COMMIT() asm volatile("cp.async.commit_group;" ::: "memory")
#define CP_WAIT1()  asm volatile("cp.async.wait_group 1;" ::: "memory")
#define BAR_SYNC(id, cnt) \
    asm volatile("bar.sync %0, %1;" :: "r"(id), "r"(cnt) : "memory")

// packed f32x2 (Blackwell)
__device__ __forceinline__ ull pack2(float lo, float hi) {
    ull r;
    asm("mov.b64 %0, {%1, %2};" : "=l"(r) : "f"(lo), "f"(hi));
    return r;
}
__device__ __forceinline__ void unpack2(ull v, float& lo, float& hi) {
    asm("mov.b64 {%0, %1}, %2;" : "=f"(lo), "=f"(hi) : "l"(v));
}
__device__ __forceinline__ ull add2(ull a, ull b) {
    ull r;
    asm("add.rn.f32x2 %0, %1, %2;" : "=l"(r) : "l"(a), "l"(b));
    return r;
}
__device__ __forceinline__ void fma2(ull& d, ull a, ull b) {
    asm("fma.rn.f32x2 %0, %1, %2, %0;" : "+l"(d) : "l"(a), "l"(b));
}
__device__ __forceinline__ ull relu2(ull s) {
    float lo, hi;
    unpack2(s, lo, hi);
    lo = fmaxf(lo, 0.f);
    hi = fmaxf(hi, 0.f);
    return pack2(lo, hi);
}

// ---------------------------------------------------------------------------
// Kernel 1: fused SAT (row + col prefix) per (b, 32-d chunk).
// ---------------------------------------------------------------------------
#define DCH 32
__global__ void sat_fused_kernel(const float* __restrict__ pt) {
    extern __shared__ float sp[];     // [25][25][32]
    int b = blockIdx.x;
    int dc = blockIdx.y;
    int tid = threadIdx.x;
    int d = tid % DCH;
    int grp = tid / DCH;
    int dbase = dc * DCH;

    const float* base = pt + ((size_t)b * TT + 1) * DD + dbase + d;

    #pragma unroll
    for (int yy = 0; yy < 3; yy++) {
        int y = grp + yy * 8;
        const float* rp = base + (size_t)y * TH * DD;
        float* srow = sp + (size_t)(y + 1) * SW * DCH + d;
        float acc = 0.f;
        #pragma unroll
        for (int x = 0; x < TH; x++) {
            acc += rp[(size_t)x * DD];
            srow[(x + 1) * DCH] = acc;
        }
    }
    __syncthreads();

    float* gs = g_sat + ((size_t)b * SW * SW) * DD + dbase + d;
    #pragma unroll
    for (int xx = 0; xx < 3; xx++) {
        int x = grp + xx * 8;
        float acc = 0.f;
        #pragma unroll
        for (int y = 1; y < SW; y++) {
            acc += sp[((size_t)y * SW + (x + 1)) * DCH + d];
            gs[((size_t)y * SW + (x + 1)) * DD] = acc;
        }
    }
}

// ---------------------------------------------------------------------------
// Kernel 2: ROI mean via SAT lookup -> fp16 operand A.
// ---------------------------------------------------------------------------
__global__ void pool_lookup_kernel(const float* __restrict__ boxes,
                                   const int* __restrict__ imh,
                                   const int* __restrict__ imw) {
    int idx = blockIdx.x * 256 + threadIdx.x;
    int d = idx % DD;
    int bn = idx / DD;
    int b = bn / NN;

    const float* box = boxes + (size_t)bn * 4;
    float sizeW = (float)(*imw);
    float sizeH = (float)(*imh);

    int px1 = (int)floorf(floorf(box[0] * sizeW) / sizeW * (float)TH);
    int py1 = (int)floorf(floorf(box[1] * sizeH) / sizeH * (float)TH);
    int px2 = (int)floorf(floorf(box[2] * sizeW) / sizeW * (float)TH);
    int py2 = (int)floorf(floorf(box[3] * sizeH) / sizeH * (float)TH);
    px1 = min(max(px1, 0), TH - 1);
    py1 = min(max(py1, 0), TH - 1);
    px2 = min(max(px2, 1), TH);
    py2 = min(max(py2, 1), TH);
    if (px2 <= px1) px2 = px1 + 1;
    if (py2 <= py1) py2 = py1 + 1;

    float inv_cnt = 1.f / (float)((px2 - px1) * (py2 - py1));

    const float* S = g_sat + ((size_t)b * SW * SW) * DD + d;
    float s22 = S[((size_t)py2 * SW + px2) * DD];
    float s12 = S[((size_t)py1 * SW + px2) * DD];
    float s21 = S[((size_t)py2 * SW + px1) * DD];
    float s11 = S[((size_t)py1 * SW + px1) * DD];

    float p = (s22 - s12 - s21 + s11) * inv_cnt;
    ((__half*)g_pA)[(size_t)bn * DD + d] = __float2half_rn(p);
}

// ---------------------------------------------------------------------------
// Kernel 3: transpose W1 -> fp16.
// ---------------------------------------------------------------------------
__global__ void convert_w_kernel(const float* __restrict__ W1) {
    __shared__ float tile[32][33];
    int s = blockIdx.z;
    int k0 = blockIdx.x * 32;
    int n0 = blockIdx.y * 32;
    int tx = threadIdx.x % 32, ty = threadIdx.x / 32;

    #pragma unroll
    for (int j = 0; j < 4; j++) {
        int k = k0 + ty + j * 8;
        tile[ty + j * 8][tx] = W1[((size_t)(s * DD + k)) * HH + n0 + tx];
    }
    __syncthreads();

    __half* W = (__half*)g_wt;
    #pragma unroll
    for (int j = 0; j < 4; j++) {
        int n = n0 + ty + j * 8;
        float v = tile[tx][ty + j * 8];
        W[((size_t)(s * HH + n)) * DD + k0 + tx] = __float2half_rn(v);
    }
}

// ---------------------------------------------------------------------------
// Kernel 4: HMMA fp16 GEMM with in-CTA k-split + per-group named barriers.
// CTA 64x64, 256 threads = 8 warps in 2 independent k-groups of 4 warps.
// Each group: warp tile 32x32, group-local chunks, own cp.async double
// buffer, own named barrier (1+g) -> pipelines fully decoupled.
// Group 1 accs reduced into group 0.  grid (24,13)=312, ~17 warps/SM.
// ---------------------------------------------------------------------------
#define KCH 32
#define NCHUNK (DD / KCH)     // 24
#define HCH (NCHUNK / 2)      // 12 chunks per group
#define PITCHB 80             // 32 fp16 = 64B + 16B pad
#define T_A 0                 // 64 rows * 80B = 5120
#define T_B 5120
#define BUFSZ 10240
#define GSMEM (4 * BUFSZ)     // 40960 static (2 buffers x 2 groups)

__global__ void __launch_bounds__(256)
hmma_gemm_kernel(const float* __restrict__ b1) {
    __shared__ __align__(16) char smem[GSMEM];
    uint32_t sb = smem_u32(smem);

    int tid = threadIdx.x;                   // 0..255
    int wid = tid / 32, lid = tid % 32;
    int g = wid >> 2;                        // k-group 0/1
    int wg = wid & 3;                        // warp within group
    int wy = wg & 1, wx = wg >> 1;           // warp tile (wy*32 m, wx*32 n)
    int tl = tid & 127;                      // thread within group
    int bar = 1 + g;                         // named barrier per group

    int nt = blockIdx.x;                     // 0..23
    int m0 = blockIdx.y * 64;
    int nrow0 = nt * 64;                     // row base into Wt

    const char* A = (const char*)g_pA;
    const char* B = (const char*)g_wt;

    uint32_t gbase = sb + (uint32_t)g * 2 * BUFSZ;

    // cp.async mapping: 64 rows x 4 granules = 256 slots, 2 iters of 128
    auto load_chunk = [&](int buf, int ch) {     // ch group-local 0..11
        uint32_t bufb = gbase + buf * BUFSZ;
        int kb = (g * HCH + ch) * KCH;
        #pragma unroll
        for (int t = 0; t < 2; t++) {
            int idx = tl + t * 128;
            int r = idx >> 2, gr = idx & 3;
            uint32_t off = (uint32_t)(r * PITCHB + gr * 16);
            size_t oa = ((size_t)(m0 + r) * DD + kb) * 2 + (size_t)gr * 16;
            size_t ob = ((size_t)(nrow0 + r) * DD + kb) * 2 + (size_t)gr * 16;
            cp16(bufb + T_A + off, A + oa);
            cp16(bufb + T_B + off, B + ob);
        }
    };

    float acc[2][4][4] = {};                 // warp 32x32: mf2 x nf4

    load_chunk(0, 0);
    CP_COMMIT();
    load_chunk(1, 1);
    CP_COMMIT();

    int la_row = lid % 16, la_blk = lid / 16;
    int lb_row = lid % 8, lb_blk = (lid / 8) & 1;

    for (int ch = 0; ch < HCH; ch++) {
        CP_WAIT1();
        BAR_SYNC(bar, 128);

        uint32_t bufb = gbase + (ch & 1) * BUFSZ;

        #pragma unroll
        for (int ks = 0; ks < 2; ks++) {
            int kofs = ks * 16;
            uint32_t a[2][4], b[4][2];

            #pragma unroll
            for (int mf = 0; mf < 2; mf++) {
                uint32_t ad = bufb + (uint32_t)((wy * 32 + mf * 16 + la_row) * PITCHB
                                                + (kofs + la_blk * 8) * 2);
                ldm_x4(a[mf], T_A + ad);
            }
            #pragma unroll
            for (int nf = 0; nf < 4; nf++) {
                uint32_t bd = bufb + (uint32_t)((wx * 32 + nf * 8 + lb_row) * PITCHB
                                                + (kofs + lb_blk * 8) * 2);
                ldm_x2(b[nf], T_B + bd);
            }

            #pragma unroll
            for (int mf = 0; mf < 2; mf++) {
                #pragma unroll
                for (int nf = 0; nf < 4; nf++) {
                    mma16816h(acc[mf][nf], a[mf], b[nf]);
                }
            }
        }
        BAR_SYNC(bar, 128);

        if (ch + 2 < HCH) load_chunk(ch & 1, ch + 2);
        CP_COMMIT();
    }

    // Cross-group reduction: group 1 spills accs, group 0 adds.
    // Layout red[q][tl] (q = 0..31), 16 KB: conflict-free.
    float* red = (float*)smem;
    __syncthreads();                         // both groups fully done
    if (g == 1) {
        int q = 0;
        #pragma unroll
        for (int mf = 0; mf < 2; mf++)
            #pragma unroll
            for (int nf = 0; nf < 4; nf++)
                #pragma unroll
                for (int e = 0; e < 4; e++)
                    red[(q++) * 128 + tl] = acc[mf][nf][e];
    }
    __syncthreads();
    if (g == 1) return;

    {
        int q = 0;
        #pragma unroll
        for (int mf = 0; mf < 2; mf++)
            #pragma unroll
            for (int nf = 0; nf < 4; nf++)
                #pragma unroll
                for (int e = 0; e < 4; e++)
                    acc[mf][nf][e] += red[(q++) * 128 + tl];
    }

    // Epilogue: fold b1 for the ha half, store float2 pairs
    bool is_ha = (nt < 12);
    float* C = is_ha ? g_ha : g_hb;
    int n0 = (is_ha ? nt : nt - 12) * 64;

    #pragma unroll
    for (int mf = 0; mf < 2; mf++) {
        #pragma unroll
        for (int nf = 0; nf < 4; nf++) {
            int m = m0 + wy * 32 + mf * 16 + lid / 4;
            int n = n0 + wx * 32 + nf * 8 + 2 * (lid % 4);
            float2 bia = make_float2(0.f, 0.f);
            if (is_ha) bia = *(const float2*)(b1 + n);
            if (m < BN) {
                float2 v = make_float2(acc[mf][nf][0] + bia.x,
                                       acc[mf][nf][1] + bia.y);
                *(float2*)(C + (size_t)m * HH + n) = v;
            }
            if (m + 8 < BN) {
                float2 v = make_float2(acc[mf][nf][2] + bia.x,
                                       acc[mf][nf][3] + bia.y);
                *(float2*)(C + (size_t)(m + 8) * HH + n) = v;
            }
        }
    }
}

// ---------------------------------------------------------------------------
// Kernel 5a: pairwise relu-dot partials, k-split into 4 quarters.
// ---------------------------------------------------------------------------
#define KC 64
#define KQ (HH / 4)           // 192
__global__ void pair_part_kernel(const float* __restrict__ W2) {
    int z = blockIdx.z;
    int b = z >> 2;
    int kq = z & 3;
    int i0 = blockIdx.y * 32;
    int j0 = blockIdx.x * 32;

    __shared__ float has[32][KC + 4];
    __shared__ float hbs[32][KC + 4];
    __shared__ float w2s[KC];

    int tid = threadIdx.x;
    int tx = tid % 16, ty = tid / 16;

    ull acc[2][2];
    acc[0][0] = acc[0][1] = acc[1][0] = acc[1][1] = pack2(0.f, 0.f);

    int kbeg = kq * KQ;
    for (int k0 = kbeg; k0 < kbeg + KQ; k0 += KC) {
        #pragma unroll
        for (int t = 0; t < 2; t++) {
            int idx = tid + t * 256;
            int r = idx / 16, c4 = idx % 16;
            int i = i0 + r;
            float4 va = make_float4(0.f, 0.f, 0.f, 0.f);
            if (i < NN) va = *(const float4*)&g_ha[((size_t)b * NN + i) * HH + k0 + c4 * 4];
            *(float4*)&has[r][c4 * 4] = va;
            int j = j0 + r;
            float4 vb = make_float4(0.f, 0.f, 0.f, 0.f);
            if (j < NN) vb = *(const float4*)&g_hb[((size_t)b * NN + j) * HH + k0 + c4 * 4];
            *(float4*)&hbs[r][c4 * 4] = vb;
        }
        if (tid < KC / 4)
            *(float4*)&w2s[tid * 4] = *(const float4*)&W2[k0 + tid * 4];
        __syncthreads();

        #pragma unroll
        for (int kk = 0; kk < KC; kk += 4) {
            float4 a0 = *(const float4*)&has[ty * 2][kk];
            float4 a1 = *(const float4*)&has[ty * 2 + 1][kk];
            float4 c0 = *(const float4*)&hbs[tx * 2][kk];
            float4 c1 = *(const float4*)&hbs[tx * 2 + 1][kk];
            float4 w  = *(const float4*)&w2s[kk];

            ull a0p0 = pack2(a0.x, a0.y), a0p1 = pack2(a0.z, a0.w);
            ull a1p0 = pack2(a1.x, a1.y), a1p1 = pack2(a1.z, a1.w);
            ull c0p0 = pack2(c0.x, c0.y), c0p1 = pack2(c0.z, c0.w);
            ull c1p0 = pack2(c1.x, c1.y), c1p1 = pack2(c1.z, c1.w);
            ull wp0  = pack2(w.x, w.y),   wp1  = pack2(w.z, w.w);

            fma2(acc[0][0], relu2(add2(a0p0, c0p0)), wp0);
            fma2(acc[0][0], relu2(add2(a0p1, c0p1)), wp1);
            fma2(acc[0][1], relu2(add2(a0p0, c1p0)), wp0);
            fma2(acc[0][1], relu2(add2(a0p1, c1p1)), wp1);
            fma2(acc[1][0], relu2(add2(a1p0, c0p0)), wp0);
            fma2(acc[1][0], relu2(add2(a1p1, c0p1)), wp1);
            fma2(acc[1][1], relu2(add2(a1p0, c1p0)), wp0);
            fma2(acc[1][1], relu2(add2(a1p1, c1p1)), wp1);
        }
        __syncthreads();
    }

    float* P = g_part + (size_t)kq * BB * NN * NN + (size_t)b * NN * NN;
    #pragma unroll
    for (int ii = 0; ii < 2; ii++) {
        #pragma unroll
        for (int jj = 0; jj < 2; jj++) {
            int i = i0 + ty * 2 + ii;
            int j = j0 + tx * 2 + jj;
            if (i < NN && j < NN) {
                float lo, hi;
                unpack2(acc[ii][jj], lo, hi);
                P[(size_t)i * NN + j] = lo + hi;
            }
        }
    }
}

// ---------------------------------------------------------------------------
// Kernel 5b: sum 4 partials + sigmoid.
// ---------------------------------------------------------------------------
__global__ void pair_final_kernel(const float* __restrict__ b2,
                                  float* __restrict__ out) {
    int idx = blockIdx.x * 256 + threadIdx.x;
    if (idx >= BB * NN * NN) return;
    const size_t S = (size_t)BB * NN * NN;
    float x = g_part[idx] + g_part[S + idx] + g_part[2 * S + idx]
            + g_part[3 * S + idx] + b2[0];
    out[idx] = 1.f / (1.f + expf(-x));
}

// ---------------------------------------------------------------------------
// Launch.  inputs: patch_tokens, boxes, W1, b1, W2, b2, img_h, img_w
// ---------------------------------------------------------------------------
extern "C" void kernel_launch(void* const* d_in, const int* in_sizes, int n_in,
                              void* d_out, int out_size) {
    const float* pt    = (const float*)d_in[0];
    const float* boxes = (const float*)d_in[1];
    const float* W1    = (const float*)d_in[2];
    const float* b1    = (const float*)d_in[3];
    const float* W2    = (const float*)d_in[4];
    const float* b2    = (const float*)d_in[5];
    const int*   imh   = (const int*)d_in[6];
    const int*   imw   = (const int*)d_in[7];
    float* out = (float*)d_out;

    cudaFuncSetAttribute(sat_fused_kernel,
                         cudaFuncAttributeMaxDynamicSharedMemorySize,
                         SW * SW * DCH * (int)sizeof(float));

    dim3 gs(BB, DD / DCH);            // (8, 24)
    sat_fused_kernel<<<gs, 256, SW * SW * DCH * sizeof(float)>>>(pt);

    pool_lookup_kernel<<<(BN * DD) / 256, 256>>>(boxes, imh, imw);

    dim3 gw(DD / 32, HH / 32, 2);     // (24, 24, 2)
    convert_w_kernel<<<gw, 256>>>(W1);

    dim3 gg(2 * HH / 64, (BN + 63) / 64);   // (24, 13) = 312 CTAs
    hmma_gemm_kernel<<<gg, 256>>>(b1);

    dim3 gp((NN + 31) / 32, (NN + 31) / 32, BB * 4);  // (4, 4, 32)
    pair_part_kernel<<<gp, 256>>>(W2);

    pair_final_kernel<<<(BB * NN * NN + 255) / 256, 256>>>(b2, out);
}

// round 16
// speedup vs baseline: 1.5595x; 1.1345x over previous
#include <cuda_runtime.h>
#include <cuda_fp16.h>
#include <math.h>
#include <stdint.h>

// Problem dims (fixed)
#define BB 8
#define NN 100
#define DD 768
#define HH 768
#define TT 577
#define TH 24
#define SW (TH+1)         // 25
#define BN (BB*NN)        // 800
#define MPAD 896          // zero-padded A rows

// ---------------- scratch (device globals; zero-initialized) ---------------
__device__ float g_ha[BN * HH];   // bias b1 folded in
__device__ float g_hb[BN * HH];
__device__ float g_part[4 * BB * NN * NN];   // pair k-split partials
__device__ uint4 g_pA[MPAD * DD / 8];        // [896][768] fp16, rows >=800 zero
__device__ uint4 g_wt[2 * HH * DD / 8];      // [1536][768] fp16 (row n, col k)

// ---------------- helpers --------------------------------------------------
typedef unsigned long long ull;

__device__ __forceinline__ uint32_t smem_u32(const void* p) {
    uint32_t a;
    asm("{ .reg .u64 t; cvta.to.shared.u64 t, %1; cvt.u32.u64 %0, t; }"
        : "=r"(a) : "l"(p));
    return a;
}
__device__ __forceinline__ void ldm_x4(uint32_t* r, uint32_t addr) {
    asm volatile("ldmatrix.sync.aligned.m8n8.x4.shared.b16 {%0,%1,%2,%3}, [%4];"
                 : "=r"(r[0]), "=r"(r[1]), "=r"(r[2]), "=r"(r[3]) : "r"(addr));
}
__device__ __forceinline__ void ldm_x2(uint32_t* r, uint32_t addr) {
    asm volatile("ldmatrix.sync.aligned.m8n8.x2.shared.b16 {%0,%1}, [%2];"
                 : "=r"(r[0]), "=r"(r[1]) : "r"(addr));
}
__device__ __forceinline__ void mma16816h(float* c, const uint32_t* a,
                                          const uint32_t* b) {
    asm volatile(
        "mma.sync.aligned.m16n8k16.row.col.f32.f16.f16.f32 "
        "{%0,%1,%2,%3}, {%4,%5,%6,%7}, {%8,%9}, {%0,%1,%2,%3};"
        : "+f"(c[0]), "+f"(c[1]), "+f"(c[2]), "+f"(c[3])
        : "r"(a[0]), "r"(a[1]), "r"(a[2]), "r"(a[3]), "r"(b[0]), "r"(b[1]));
}
__device__ __forceinline__ void cp16(uint32_t dst, const void* src) {
    asm volatile("cp.async.cg.shared.global [%0], [%1], 16;"
                 :: "r"(dst), "l"(src) : "memory");
}
#define CP_COMMIT() asm volatile("cp.async.commit_group;" ::: "memory")
#define CP_WAIT1()  asm volatile("cp.async.wait_group 1;" ::: "memory")
#define BAR_SYNC(id, cnt) \
    asm volatile("bar.sync %0, %1;" :: "r"(id), "r"(cnt) : "memory")

// packed f32x2 (Blackwell)
__device__ __forceinline__ ull pack2(float lo, float hi) {
    ull r;
    asm("mov.b64 %0, {%1, %2};" : "=l"(r) : "f"(lo), "f"(hi));
    return r;
}
__device__ __forceinline__ void unpack2(ull v, float& lo, float& hi) {
    asm("mov.b64 {%0, %1}, %2;" : "=f"(lo), "=f"(hi) : "l"(v));
}
__device__ __forceinline__ ull add2(ull a, ull b) {
    ull r;
    asm("add.rn.f32x2 %0, %1, %2;" : "=l"(r) : "l"(a), "l"(b));
    return r;
}
__device__ __forceinline__ void fma2(ull& d, ull a, ull b) {
    asm("fma.rn.f32x2 %0, %1, %2, %0;" : "+l"(d) : "l"(a), "l"(b));
}
__device__ __forceinline__ ull relu2(ull s) {
    float lo, hi;
    unpack2(s, lo, hi);
    lo = fmaxf(lo, 0.f);
    hi = fmaxf(hi, 0.f);
    return pack2(lo, hi);
}

// ---------------------------------------------------------------------------
// Kernel 1: fused prep.
// Blocks [0, 192): per-(b, 32-d chunk) SAT in smem + ROI pool -> fp16 A.
// Blocks [192, 1344): W1 transpose -> fp16 B.
// Dynamic smem: 25*25*32 floats (SAT plane) + 512 floats (box coords).
// ---------------------------------------------------------------------------
#define DCH 32
#define SATBLK (BB * (DD / DCH))      // 192
#define PREP_SMEM ((SW * SW * DCH + 512) * 4)   // 82048 B

__global__ void prep_kernel(const float* __restrict__ pt,
                            const float* __restrict__ boxes,
                            const int* __restrict__ imh,
                            const int* __restrict__ imw,
                            const float* __restrict__ W1) {
    extern __shared__ float sp[];
    int tid = threadIdx.x;

    if (blockIdx.x < SATBLK) {
        int b = blockIdx.x / (DD / DCH);
        int dc = blockIdx.x % (DD / DCH);
        int d = tid % DCH;
        int grp = tid / DCH;          // 0..7
        int dbase = dc * DCH;

        // zero borders: row y=0 (all x) and col x=0 (all y)
        for (int i = tid; i < SW * DCH; i += 256) {
            int q = i / DCH, dd = i % DCH;
            sp[(size_t)q * DCH + dd] = 0.f;              // y=0 row (x=q)
            sp[((size_t)q * SW) * DCH + dd] = 0.f;       // x=0 col (y=q)
        }

        // row prefix: each thread owns 3 y-rows
        const float* base = pt + ((size_t)b * TT + 1) * DD + dbase + d;
        #pragma unroll
        for (int yy = 0; yy < 3; yy++) {
            int y = grp + yy * 8;
            const float* rp = base + (size_t)y * TH * DD;
            float* srow = sp + (size_t)(y + 1) * SW * DCH + d;
            float acc = 0.f;
            #pragma unroll
            for (int x = 0; x < TH; x++) {
                acc += rp[(size_t)x * DD];
                srow[(x + 1) * DCH] = acc;
            }
        }
        __syncthreads();

        // col prefix in place: each thread owns 3 x-cols
        #pragma unroll
        for (int xx = 0; xx < 3; xx++) {
            int x = grp + xx * 8;
            float acc = 0.f;
            #pragma unroll
            for (int y = 1; y < SW; y++) {
                float* p = sp + ((size_t)y * SW + (x + 1)) * DCH + d;
                acc += *p;
                *p = acc;
            }
        }

        // box coords (exact fp32 chain as reference)
        float* cbuf = sp + SW * SW * DCH;   // [5][100] + pad
        if (tid < NN) {
            const float* box = boxes + ((size_t)b * NN + tid) * 4;
            float sizeW = (float)(*imw);
            float sizeH = (float)(*imh);
            int px1 = (int)floorf(floorf(box[0] * sizeW) / sizeW * (float)TH);
            int py1 = (int)floorf(floorf(box[1] * sizeH) / sizeH * (float)TH);
            int px2 = (int)floorf(floorf(box[2] * sizeW) / sizeW * (float)TH);
            int py2 = (int)floorf(floorf(box[3] * sizeH) / sizeH * (float)TH);
            px1 = min(max(px1, 0), TH - 1);
            py1 = min(max(py1, 0), TH - 1);
            px2 = min(max(px2, 1), TH);
            py2 = min(max(py2, 1), TH);
            if (px2 <= px1) px2 = px1 + 1;
            if (py2 <= py1) py2 = py1 + 1;
            cbuf[tid]       = (float)px1;
            cbuf[100 + tid] = (float)py1;
            cbuf[200 + tid] = (float)px2;
            cbuf[300 + tid] = (float)py2;
            cbuf[400 + tid] = 1.f / (float)((px2 - px1) * (py2 - py1));
        }
        __syncthreads();

        // ROI lookups straight from smem SAT plane
        __half* Adst = (__half*)g_pA;
        for (int n = grp; n < NN; n += 8) {
            int px1 = (int)cbuf[n];
            int py1 = (int)cbuf[100 + n];
            int px2 = (int)cbuf[200 + n];
            int py2 = (int)cbuf[300 + n];
            float inv_cnt = cbuf[400 + n];
            float s22 = sp[((size_t)py2 * SW + px2) * DCH + d];
            float s12 = sp[((size_t)py1 * SW + px2) * DCH + d];
            float s21 = sp[((size_t)py2 * SW + px1) * DCH + d];
            float s11 = sp[((size_t)py1 * SW + px1) * DCH + d];
            float p = (s22 - s12 - s21 + s11) * inv_cnt;
            Adst[((size_t)b * NN + n) * DD + dbase + d] = __float2half_rn(p);
        }
    } else {
        // W1 transpose -> fp16  (1152 blocks: s,k0,n0)
        int idx = blockIdx.x - SATBLK;
        int s = idx / 576;
        idx %= 576;
        int k0 = (idx / 24) * 32;
        int n0 = (idx % 24) * 32;
        float* tile = sp;             // [32][33]
        int tx = tid % 32, ty = tid / 32;

        #pragma unroll
        for (int j = 0; j < 4; j++) {
            int k = k0 + ty + j * 8;
            tile[(ty + j * 8) * 33 + tx] = W1[((size_t)(s * DD + k)) * HH + n0 + tx];
        }
        __syncthreads();

        __half* W = (__half*)g_wt;
        #pragma unroll
        for (int j = 0; j < 4; j++) {
            int n = n0 + ty + j * 8;
            float v = tile[tx * 33 + ty + j * 8];
            W[((size_t)(s * HH + n)) * DD + k0 + tx] = __float2half_rn(v);
        }
    }
}

// ---------------------------------------------------------------------------
// Kernel 2: HMMA fp16 GEMM with in-CTA k-split + per-group named barriers.
// (round-15 version, proven)
// ---------------------------------------------------------------------------
#define KCH 32
#define NCHUNK (DD / KCH)     // 24
#define HCH (NCHUNK / 2)      // 12 chunks per group
#define PITCHB 80
#define T_A 0
#define T_B 5120
#define BUFSZ 10240
#define GSMEM (4 * BUFSZ)     // 40960 static

__global__ void __launch_bounds__(256)
hmma_gemm_kernel(const float* __restrict__ b1) {
    __shared__ __align__(16) char smem[GSMEM];
    uint32_t sb = smem_u32(smem);

    int tid = threadIdx.x;
    int wid = tid / 32, lid = tid % 32;
    int g = wid >> 2;
    int wg = wid & 3;
    int wy = wg & 1, wx = wg >> 1;
    int tl = tid & 127;
    int bar = 1 + g;

    int nt = blockIdx.x;
    int m0 = blockIdx.y * 64;
    int nrow0 = nt * 64;

    const char* A = (const char*)g_pA;
    const char* B = (const char*)g_wt;

    uint32_t gbase = sb + (uint32_t)g * 2 * BUFSZ;

    auto load_chunk = [&](int buf, int ch) {
        uint32_t bufb = gbase + buf * BUFSZ;
        int kb = (g * HCH + ch) * KCH;
        #pragma unroll
        for (int t = 0; t < 2; t++) {
            int idx = tl + t * 128;
            int r = idx >> 2, gr = idx & 3;
            uint32_t off = (uint32_t)(r * PITCHB + gr * 16);
            size_t oa = ((size_t)(m0 + r) * DD + kb) * 2 + (size_t)gr * 16;
            size_t ob = ((size_t)(nrow0 + r) * DD + kb) * 2 + (size_t)gr * 16;
            cp16(bufb + T_A + off, A + oa);
            cp16(bufb + T_B + off, B + ob);
        }
    };

    float acc[2][4][4] = {};

    load_chunk(0, 0);
    CP_COMMIT();
    load_chunk(1, 1);
    CP_COMMIT();

    int la_row = lid % 16, la_blk = lid / 16;
    int lb_row = lid % 8, lb_blk = (lid / 8) & 1;

    for (int ch = 0; ch < HCH; ch++) {
        CP_WAIT1();
        BAR_SYNC(bar, 128);

        uint32_t bufb = gbase + (ch & 1) * BUFSZ;

        #pragma unroll
        for (int ks = 0; ks < 2; ks++) {
            int kofs = ks * 16;
            uint32_t a[2][4], b[4][2];

            #pragma unroll
            for (int mf = 0; mf < 2; mf++) {
                uint32_t ad = bufb + (uint32_t)((wy * 32 + mf * 16 + la_row) * PITCHB
                                                + (kofs + la_blk * 8) * 2);
                ldm_x4(a[mf], T_A + ad);
            }
            #pragma unroll
            for (int nf = 0; nf < 4; nf++) {
                uint32_t bd = bufb + (uint32_t)((wx * 32 + nf * 8 + lb_row) * PITCHB
                                                + (kofs + lb_blk * 8) * 2);
                ldm_x2(b[nf], T_B + bd);
            }

            #pragma unroll
            for (int mf = 0; mf < 2; mf++) {
                #pragma unroll
                for (int nf = 0; nf < 4; nf++) {
                    mma16816h(acc[mf][nf], a[mf], b[nf]);
                }
            }
        }
        BAR_SYNC(bar, 128);

        if (ch + 2 < HCH) load_chunk(ch & 1, ch + 2);
        CP_COMMIT();
    }

    // Cross-group reduction
    float* red = (float*)smem;
    __syncthreads();
    if (g == 1) {
        int q = 0;
        #pragma unroll
        for (int mf = 0; mf < 2; mf++)
            #pragma unroll
            for (int nf = 0; nf < 4; nf++)
                #pragma unroll
                for (int e = 0; e < 4; e++)
                    red[(q++) * 128 + tl] = acc[mf][nf][e];
    }
    __syncthreads();
    if (g == 1) return;

    {
        int q = 0;
        #pragma unroll
        for (int mf = 0; mf < 2; mf++)
            #pragma unroll
            for (int nf = 0; nf < 4; nf++)
                #pragma unroll
                for (int e = 0; e < 4; e++)
                    acc[mf][nf][e] += red[(q++) * 128 + tl];
    }

    bool is_ha = (nt < 12);
    float* C = is_ha ? g_ha : g_hb;
    int n0 = (is_ha ? nt : nt - 12) * 64;

    #pragma unroll
    for (int mf = 0; mf < 2; mf++) {
        #pragma unroll
        for (int nf = 0; nf < 4; nf++) {
            int m = m0 + wy * 32 + mf * 16 + lid / 4;
            int n = n0 + wx * 32 + nf * 8 + 2 * (lid % 4);
            float2 bia = make_float2(0.f, 0.f);
            if (is_ha) bia = *(const float2*)(b1 + n);
            if (m < BN) {
                float2 v = make_float2(acc[mf][nf][0] + bia.x,
                                       acc[mf][nf][1] + bia.y);
                *(float2*)(C + (size_t)m * HH + n) = v;
            }
            if (m + 8 < BN) {
                float2 v = make_float2(acc[mf][nf][2] + bia.x,
                                       acc[mf][nf][3] + bia.y);
                *(float2*)(C + (size_t)(m + 8) * HH + n) = v;
            }
        }
    }
}

// ---------------------------------------------------------------------------
// Kernel 3a: pairwise relu-dot partials, k-split into 4 quarters.
// ---------------------------------------------------------------------------
#define KC 64
#define KQ (HH / 4)           // 192
__global__ void pair_part_kernel(const float* __restrict__ W2) {
    int z = blockIdx.z;
    int b = z >> 2;
    int kq = z & 3;
    int i0 = blockIdx.y * 32;
    int j0 = blockIdx.x * 32;

    __shared__ float has[32][KC + 4];
    __shared__ float hbs[32][KC + 4];
    __shared__ float w2s[KC];

    int tid = threadIdx.x;
    int tx = tid % 16, ty = tid / 16;

    ull acc[2][2];
    acc[0][0] = acc[0][1] = acc[1][0] = acc[1][1] = pack2(0.f, 0.f);

    int kbeg = kq * KQ;
    for (int k0 = kbeg; k0 < kbeg + KQ; k0 += KC) {
        #pragma unroll
        for (int t = 0; t < 2; t++) {
            int idx = tid + t * 256;
            int r = idx / 16, c4 = idx % 16;
            int i = i0 + r;
            float4 va = make_float4(0.f, 0.f, 0.f, 0.f);
            if (i < NN) va = *(const float4*)&g_ha[((size_t)b * NN + i) * HH + k0 + c4 * 4];
            *(float4*)&has[r][c4 * 4] = va;
            int j = j0 + r;
            float4 vb = make_float4(0.f, 0.f, 0.f, 0.f);
            if (j < NN) vb = *(const float4*)&g_hb[((size_t)b * NN + j) * HH + k0 + c4 * 4];
            *(float4*)&hbs[r][c4 * 4] = vb;
        }
        if (tid < KC / 4)
            *(float4*)&w2s[tid * 4] = *(const float4*)&W2[k0 + tid * 4];
        __syncthreads();

        #pragma unroll
        for (int kk = 0; kk < KC; kk += 4) {
            float4 a0 = *(const float4*)&has[ty * 2][kk];
            float4 a1 = *(const float4*)&has[ty * 2 + 1][kk];
            float4 c0 = *(const float4*)&hbs[tx * 2][kk];
            float4 c1 = *(const float4*)&hbs[tx * 2 + 1][kk];
            float4 w  = *(const float4*)&w2s[kk];

            ull a0p0 = pack2(a0.x, a0.y), a0p1 = pack2(a0.z, a0.w);
            ull a1p0 = pack2(a1.x, a1.y), a1p1 = pack2(a1.z, a1.w);
            ull c0p0 = pack2(c0.x, c0.y), c0p1 = pack2(c0.z, c0.w);
            ull c1p0 = pack2(c1.x, c1.y), c1p1 = pack2(c1.z, c1.w);
            ull wp0  = pack2(w.x, w.y),   wp1  = pack2(w.z, w.w);

            fma2(acc[0][0], relu2(add2(a0p0, c0p0)), wp0);
            fma2(acc[0][0], relu2(add2(a0p1, c0p1)), wp1);
            fma2(acc[0][1], relu2(add2(a0p0, c1p0)), wp0);
            fma2(acc[0][1], relu2(add2(a0p1, c1p1)), wp1);
            fma2(acc[1][0], relu2(add2(a1p0, c0p0)), wp0);
            fma2(acc[1][0], relu2(add2(a1p1, c0p1)), wp1);
            fma2(acc[1][1], relu2(add2(a1p0, c1p0)), wp0);
            fma2(acc[1][1], relu2(add2(a1p1, c1p1)), wp1);
        }
        __syncthreads();
    }

    float* P = g_part + (size_t)kq * BB * NN * NN + (size_t)b * NN * NN;
    #pragma unroll
    for (int ii = 0; ii < 2; ii++) {
        #pragma unroll
        for (int jj = 0; jj < 2; jj++) {
            int i = i0 + ty * 2 + ii;
            int j = j0 + tx * 2 + jj;
            if (i < NN && j < NN) {
                float lo, hi;
                unpack2(acc[ii][jj], lo, hi);
                P[(size_t)i * NN + j] = lo + hi;
            }
        }
    }
}

// ---------------------------------------------------------------------------
// Kernel 3b: sum 4 partials + sigmoid.
// ---------------------------------------------------------------------------
__global__ void pair_final_kernel(const float* __restrict__ b2,
                                  float* __restrict__ out) {
    int idx = blockIdx.x * 256 + threadIdx.x;
    if (idx >= BB * NN * NN) return;
    const size_t S = (size_t)BB * NN * NN;
    float x = g_part[idx] + g_part[S + idx] + g_part[2 * S + idx]
            + g_part[3 * S + idx] + b2[0];
    out[idx] = 1.f / (1.f + expf(-x));
}

// ---------------------------------------------------------------------------
// Launch.  inputs: patch_tokens, boxes, W1, b1, W2, b2, img_h, img_w
// ---------------------------------------------------------------------------
extern "C" void kernel_launch(void* const* d_in, const int* in_sizes, int n_in,
                              void* d_out, int out_size) {
    const float* pt    = (const float*)d_in[0];
    const float* boxes = (const float*)d_in[1];
    const float* W1    = (const float*)d_in[2];
    const float* b1    = (const float*)d_in[3];
    const float* W2    = (const float*)d_in[4];
    const float* b2    = (const float*)d_in[5];
    const int*   imh   = (const int*)d_in[6];
    const int*   imw   = (const int*)d_in[7];
    float* out = (float*)d_out;

    cudaFuncSetAttribute(prep_kernel,
                         cudaFuncAttributeMaxDynamicSharedMemorySize, PREP_SMEM);

    prep_kernel<<<SATBLK + 2 * 24 * 24, 256, PREP_SMEM>>>(pt, boxes, imh, imw, W1);

    dim3 gg(2 * HH / 64, (BN + 63) / 64);   // (24, 13) = 312 CTAs
    hmma_gemm_kernel<<<gg, 256>>>(b1);

    dim3 gp((NN + 31) / 32, (NN + 31) / 32, BB * 4);  // (4, 4, 32)
    pair_part_kernel<<<gp, 256>>>(W2);

    pair_final_kernel<<<(BB * NN * NN + 255) / 256, 256>>>(b2, out);
}